// round 15
// baseline (speedup 1.0000x reference)
#include <cuda_runtime.h>
#include <cuda_fp16.h>
#include <math.h>
#include <cstdint>

// Problem constants
#define B_ 2
#define S_ 2048
#define D_ 4096
#define H_ 32
#define KV_ 8
#define HD_ 128

// ---------------------------------------------------------------------------
// Scratch (static __device__ per allocation rules)
// ---------------------------------------------------------------------------
__device__ float g_cos[(size_t)B_ * S_ * 64];
__device__ float g_sin[(size_t)B_ * S_ * 64];
// fp16 tensors
__device__ __half g_hsH[(size_t)B_ * S_ * D_];
__device__ __half g_WqH[(size_t)H_ * HD_ * D_];
__device__ __half g_WkH[(size_t)KV_ * HD_ * D_];
__device__ __half g_WvH[(size_t)KV_ * HD_ * D_];
__device__ __half g_WoH[(size_t)D_ * H_ * HD_];
__device__ __half g_QH[(size_t)B_ * H_ * S_ * HD_];  // roped, pre-scaled
__device__ __half g_KH[(size_t)B_ * KV_ * S_ * HD_]; // roped
__device__ __half g_VH[(size_t)B_ * KV_ * S_ * HD_]; // from GEMM epilogue
__device__ __half g_AOH[(size_t)B_ * S_ * H_ * HD_]; // flash out [B,S,H,HD]

// ---------------------------------------------------------------------------
// Helpers
// ---------------------------------------------------------------------------
__device__ __forceinline__ uint32_t smem_u32(const void* p) {
    uint32_t a;
    asm("{ .reg .u64 t; cvta.to.shared.u64 t, %1; cvt.u32.u64 %0, t; }"
        : "=r"(a) : "l"(p));
    return a;
}
__device__ __forceinline__ uint32_t h2_as_u32(__half2 h) {
    union { __half2 h; uint32_t u; } cvt;
    cvt.h = h;
    return cvt.u;
}
__device__ __forceinline__ void cp_async16(uint32_t saddr, const void* g) {
    asm volatile("cp.async.cg.shared.global [%0], [%1], 16;" :: "r"(saddr), "l"(g));
}
#define CP_COMMIT() asm volatile("cp.async.commit_group;" ::: "memory")
template <int N>
__device__ __forceinline__ void cp_wait() {
    asm volatile("cp.async.wait_group %0;" :: "n"(N) : "memory");
}
__device__ __forceinline__ void ldsm_x4(uint32_t* r, uint32_t addr) {
    asm volatile("ldmatrix.sync.aligned.m8n8.x4.shared.b16 {%0,%1,%2,%3}, [%4];"
                 : "=r"(r[0]), "=r"(r[1]), "=r"(r[2]), "=r"(r[3]) : "r"(addr));
}
__device__ __forceinline__ void ldsm_x4_t(uint32_t* r, uint32_t addr) {
    asm volatile("ldmatrix.sync.aligned.m8n8.x4.trans.shared.b16 {%0,%1,%2,%3}, [%4];"
                 : "=r"(r[0]), "=r"(r[1]), "=r"(r[2]), "=r"(r[3]) : "r"(addr));
}
__device__ __forceinline__ void ldsm_x2(uint32_t* r, uint32_t addr) {
    asm volatile("ldmatrix.sync.aligned.m8n8.x2.shared.b16 {%0,%1}, [%2];"
                 : "=r"(r[0]), "=r"(r[1]) : "r"(addr));
}
__device__ __forceinline__ void mma16816(float* c, const uint32_t* a, const uint32_t* b) {
    asm volatile(
        "mma.sync.aligned.m16n8k16.row.col.f32.f16.f16.f32 "
        "{%0,%1,%2,%3}, {%4,%5,%6,%7}, {%8,%9}, {%0,%1,%2,%3};"
        : "+f"(c[0]), "+f"(c[1]), "+f"(c[2]), "+f"(c[3])
        : "r"(a[0]), "r"(a[1]), "r"(a[2]), "r"(a[3]), "r"(b[0]), "r"(b[1]));
}

// ---------------------------------------------------------------------------
// Merged fp32 -> fp16 conversion for all 5 tensors, MLP=4 per segment.
// Quarter-segment sizes (in float4): hs/Wq/Wo = 1M, Wk/Wv = 256K.
// ---------------------------------------------------------------------------
#define CVT_Q1 (1 << 20)
#define CVT_Q2 (1 << 18)
#define CVT_THREADS (3 * CVT_Q1 + 2 * CVT_Q2)

__global__ void convert_all_kernel(const float* __restrict__ hs,
                                   const float* __restrict__ Wq,
                                   const float* __restrict__ Wk,
                                   const float* __restrict__ Wv,
                                   const float* __restrict__ Wo,
                                   __half* o_hs, __half* o_q, __half* o_k,
                                   __half* o_v, __half* o_o) {
    int gid = blockIdx.x * blockDim.x + threadIdx.x;
    if (gid >= CVT_THREADS) return;
    const float* in;
    __half* out;
    int q, base;
    if (gid < CVT_Q1)            { in = hs; out = o_hs; q = CVT_Q1; base = gid; }
    else if (gid < 2 * CVT_Q1)   { in = Wq; out = o_q;  q = CVT_Q1; base = gid - CVT_Q1; }
    else if (gid < 2 * CVT_Q1 + CVT_Q2)     { in = Wk; out = o_k; q = CVT_Q2; base = gid - 2 * CVT_Q1; }
    else if (gid < 2 * CVT_Q1 + 2 * CVT_Q2) { in = Wv; out = o_v; q = CVT_Q2; base = gid - 2 * CVT_Q1 - CVT_Q2; }
    else                         { in = Wo; out = o_o;  q = CVT_Q1; base = gid - 2 * CVT_Q1 - 2 * CVT_Q2; }
    const float4* in4 = (const float4*)in;
    uint2* o = (uint2*)out;
    float4 a = in4[base];
    float4 b = in4[base + q];
    float4 c = in4[base + 2 * q];
    float4 d = in4[base + 3 * q];
    o[base] = make_uint2(h2_as_u32(__floats2half2_rn(a.x, a.y)),
                         h2_as_u32(__floats2half2_rn(a.z, a.w)));
    o[base + q] = make_uint2(h2_as_u32(__floats2half2_rn(b.x, b.y)),
                             h2_as_u32(__floats2half2_rn(b.z, b.w)));
    o[base + 2 * q] = make_uint2(h2_as_u32(__floats2half2_rn(c.x, c.y)),
                                 h2_as_u32(__floats2half2_rn(c.z, c.w)));
    o[base + 3 * q] = make_uint2(h2_as_u32(__floats2half2_rn(d.x, d.y)),
                                 h2_as_u32(__floats2half2_rn(d.z, d.w)));
}

// ---------------------------------------------------------------------------
// RoPE tables (double-precision angles for accuracy)
// ---------------------------------------------------------------------------
__global__ void rope_table_kernel(const int* __restrict__ pos_ids) {
    int idx = blockIdx.x * blockDim.x + threadIdx.x;
    if (idx >= B_ * S_ * 64) return;
    int i = idx & 63;
    int bs = idx >> 6;
    int p = pos_ids[bs];
    double invf = exp2(-((double)(2 * i) / 128.0) * 13.287712379549449);
    double ang = (double)p * invf;
    double sd, cd;
    sincos(ang, &sd, &cd);
    g_cos[idx] = (float)cd;
    g_sin[idx] = (float)sd;
}

// ---------------------------------------------------------------------------
// HMMA GEMM core, 64x128 tile (M=64), BK=32, 4-stage cp.async, 256 threads
// (8 warps, 2x4 over 32x32 warp tiles). Same K-order as the 128-tile version
// -> bit-identical accumulation per output element.
// ---------------------------------------------------------------------------
#define PITCHB 80
#define GSTAGES 4
#define A_BYTES64 (64 * PITCHB)               // 5120
#define B_BYTES64 (128 * PITCHB)              // 10240
#define STAGE_BYTES64 (A_BYTES64 + B_BYTES64) // 15360
#define GEMM_DSMEM64 (GSTAGES * STAGE_BYTES64) // 61440

__device__ __forceinline__ void gemm_fill64(uint32_t sA, uint32_t sB,
                                            const __half* A, const __half* Bw,
                                            int m0, int n0, int K, int k0, int tid) {
    {   // A: 64 rows x 4 chunks = 256 assignments
        int row = tid >> 2, c = tid & 3;
        uint32_t off = (uint32_t)row * PITCHB + (uint32_t)c * 16;
        cp_async16(sA + off, A + (size_t)(m0 + row) * K + k0 + c * 8);
    }
#pragma unroll
    for (int i = 0; i < 2; i++) {             // B: 128 rows x 4 chunks
        int v = tid + i * 256;
        int row = v >> 2, c = v & 3;
        uint32_t off = (uint32_t)row * PITCHB + (uint32_t)c * 16;
        cp_async16(sB + off, Bw + (size_t)(n0 + row) * K + k0 + c * 8);
    }
    CP_COMMIT();
}

// Mainloop producing acc[2][4][4]; caller handles epilogue.
__device__ __forceinline__ void gemm_mainloop64(const __half* A, const __half* Bw,
                                                int m0, int n0, int K,
                                                uint32_t sBase, int tid,
                                                float acc[2][4][4]) {
    int wid = tid >> 5, l = tid & 31;
    int warpM = wid >> 2, warpN = wid & 3;    // 2 x 4
    int KT = K >> 5;

#pragma unroll
    for (int c = 0; c < GSTAGES - 1; c++) {
        uint32_t st = sBase + c * STAGE_BYTES64;
        gemm_fill64(st, st + A_BYTES64, A, Bw, m0, n0, K, c * 32, tid);
    }

    uint32_t aOff = (uint32_t)(l & 15) * PITCHB + (uint32_t)(l >> 4) * 16;
    uint32_t bOff = (uint32_t)(l & 7) * PITCHB + (uint32_t)((l >> 3) & 1) * 16;

    for (int kt = 0; kt < KT; kt++) {
        if (kt < KT - 2) cp_wait<2>();
        else if (kt == KT - 2) cp_wait<1>();
        else cp_wait<0>();
        __syncthreads();

        int nk = kt + GSTAGES - 1;
        if (nk < KT) {
            uint32_t st = sBase + (uint32_t)(nk % GSTAGES) * STAGE_BYTES64;
            gemm_fill64(st, st + A_BYTES64, A, Bw, m0, n0, K, nk * 32, tid);
        }

        uint32_t stA = sBase + (uint32_t)(kt % GSTAGES) * STAGE_BYTES64;
        uint32_t stB = stA + A_BYTES64;
        uint32_t aBase = stA + (uint32_t)(warpM * 32) * PITCHB + aOff;
        uint32_t bBase = stB + (uint32_t)(warpN * 32) * PITCHB + bOff;

#pragma unroll
        for (int ks = 0; ks < 2; ks++) {
            uint32_t kbyte = ks * 32;
            uint32_t ar[2][4], br[4][2];
#pragma unroll
            for (int mt = 0; mt < 2; mt++)
                ldsm_x4(ar[mt], aBase + (uint32_t)(mt * 16) * PITCHB + kbyte);
#pragma unroll
            for (int nt = 0; nt < 4; nt++)
                ldsm_x2(br[nt], bBase + (uint32_t)(nt * 8) * PITCHB + kbyte);
#pragma unroll
            for (int mt = 0; mt < 2; mt++)
#pragma unroll
                for (int nt = 0; nt < 4; nt++)
                    mma16816(acc[mt][nt], ar[mt], br[nt]);
        }
    }
}

// Fused QKV projection + RoPE. blockIdx.x in [0,48):
//   [0,32)  : Wq -> QH (rope + 1/sqrt(HD) scale, fp16)
//   [32,40) : Wk -> KH (rope, fp16)
//   [40,48) : Wv -> VH (fp16)
// blockIdx.y in [0,64): 64-row m-tiles.
__global__ __launch_bounds__(256, 2)
void qkv_hmma_kernel(const __half* __restrict__ A,
                     const __half* __restrict__ Wq, const __half* __restrict__ Wk,
                     const __half* __restrict__ Wv,
                     __half* __restrict__ Qo, __half* __restrict__ Ko,
                     __half* __restrict__ Vo) {
    extern __shared__ __align__(128) char dsm[];
    uint32_t sBase = smem_u32(dsm);
    int tid = threadIdx.x;
    int bx = blockIdx.x;
    int m0 = blockIdx.y * 64;

    const __half* Bw;
    int head;
    int seg;                         // 0=Q, 1=K, 2=V
    if (bx < 32)      { Bw = Wq; head = bx;      seg = 0; }
    else if (bx < 40) { Bw = Wk; head = bx - 32; seg = 1; }
    else              { Bw = Wv; head = bx - 40; seg = 2; }
    int n0 = head * 128;
    int NH = (seg == 0) ? H_ : KV_;

    float acc[2][4][4];
#pragma unroll
    for (int mt = 0; mt < 2; mt++)
#pragma unroll
        for (int nt = 0; nt < 4; nt++)
#pragma unroll
            for (int i = 0; i < 4; i++) acc[mt][nt][i] = 0.f;

    gemm_mainloop64(A, Bw, m0, n0, D_, sBase, tid, acc);

    int wid = tid >> 5, l = tid & 31;
    int warpM = wid >> 2, warpN = wid & 3;
    int rl0 = warpM * 32 + (l >> 2);
    int cl0 = warpN * 32 + (l & 3) * 2;
    int b = m0 / S_;
    int srow = m0 % S_;

    if (seg == 2) {
        __half* Cb = Vo + ((size_t)(b * NH + head) * S_ + srow) * HD_;
#pragma unroll
        for (int mt = 0; mt < 2; mt++)
#pragma unroll
            for (int nt = 0; nt < 4; nt++) {
                __half* d0 = Cb + (size_t)(rl0 + mt * 16) * HD_ + cl0 + nt * 8;
                __half* d1 = d0 + (size_t)8 * HD_;
                *(__half2*)d0 = __floats2half2_rn(acc[mt][nt][0], acc[mt][nt][1]);
                *(__half2*)d1 = __floats2half2_rn(acc[mt][nt][2], acc[mt][nt][3]);
            }
        return;
    }

    // ---- Q/K: stage fp32 tile in smem, apply RoPE, write fp16 ----
    __syncthreads();                 // mainloop smem no longer needed
    float* tileS = (float*)dsm;      // 64 x 128, pitch 132 floats (33792 B)
#pragma unroll
    for (int mt = 0; mt < 2; mt++)
#pragma unroll
        for (int nt = 0; nt < 4; nt++) {
            int r0 = rl0 + mt * 16;
            int c0 = cl0 + nt * 8;
            tileS[r0 * 132 + c0]       = acc[mt][nt][0];
            tileS[r0 * 132 + c0 + 1]   = acc[mt][nt][1];
            tileS[(r0 + 8) * 132 + c0]     = acc[mt][nt][2];
            tileS[(r0 + 8) * 132 + c0 + 1] = acc[mt][nt][3];
        }
    __syncthreads();

    __half* outp = ((seg == 0) ? Qo : Ko) +
                   ((size_t)(b * NH + head) * S_ + srow) * HD_;
    float scl = (seg == 0) ? 0.08838834764831845f : 1.0f;
    int c4 = (tid & 15) * 4;         // pair-col base (0..60)
    int rb = tid >> 4;               // 0..15
#pragma unroll
    for (int it = 0; it < 4; it++) {
        int r = rb + it * 16;
        int s = srow + r;
        float4 x1 = *(float4*)&tileS[r * 132 + c4];
        float4 x2 = *(float4*)&tileS[r * 132 + c4 + 64];
        int ti = (b * S_ + s) * 64 + c4;
        float4 cs = *(float4*)&g_cos[ti];
        float4 sn = *(float4*)&g_sin[ti];
        float o0x = (x1.x * cs.x - x2.x * sn.x) * scl;
        float o0y = (x1.y * cs.y - x2.y * sn.y) * scl;
        float o0z = (x1.z * cs.z - x2.z * sn.z) * scl;
        float o0w = (x1.w * cs.w - x2.w * sn.w) * scl;
        float o1x = (x2.x * cs.x + x1.x * sn.x) * scl;
        float o1y = (x2.y * cs.y + x1.y * sn.y) * scl;
        float o1z = (x2.z * cs.z + x1.z * sn.z) * scl;
        float o1w = (x2.w * cs.w + x1.w * sn.w) * scl;
        __half2 lo0 = __floats2half2_rn(o0x, o0y);
        __half2 lo1 = __floats2half2_rn(o0z, o0w);
        __half2 hi0 = __floats2half2_rn(o1x, o1y);
        __half2 hi1 = __floats2half2_rn(o1z, o1w);
        uint2 pk0 = make_uint2(h2_as_u32(lo0), h2_as_u32(lo1));
        uint2 pk1 = make_uint2(h2_as_u32(hi0), h2_as_u32(hi1));
        *(uint2*)&outp[(size_t)r * HD_ + c4]      = pk0;
        *(uint2*)&outp[(size_t)r * HD_ + c4 + 64] = pk1;
    }
}

// Plain GEMM (O projection): C fp32 row-major [M,N], 64-row m-tiles.
__global__ __launch_bounds__(256, 2)
void gemm_hmma_kernel(const __half* __restrict__ A, const __half* __restrict__ Bw,
                      float* __restrict__ C, int M, int N, int K) {
    extern __shared__ __align__(128) char dsm[];
    uint32_t sBase = smem_u32(dsm);
    int tid = threadIdx.x;
    int m0 = blockIdx.y * 64, n0 = blockIdx.x * 128;

    float acc[2][4][4];
#pragma unroll
    for (int mt = 0; mt < 2; mt++)
#pragma unroll
        for (int nt = 0; nt < 4; nt++)
#pragma unroll
            for (int i = 0; i < 4; i++) acc[mt][nt][i] = 0.f;

    gemm_mainloop64(A, Bw, m0, n0, K, sBase, tid, acc);

    int wid = tid >> 5, l = tid & 31;
    int warpM = wid >> 2, warpN = wid & 3;
    int rl0 = warpM * 32 + (l >> 2);
    int cl0 = warpN * 32 + (l & 3) * 2;
    float* Cb = C + (size_t)m0 * N + n0;
#pragma unroll
    for (int mt = 0; mt < 2; mt++)
#pragma unroll
        for (int nt = 0; nt < 4; nt++) {
            float* d0 = Cb + (size_t)(rl0 + mt * 16) * N + cl0 + nt * 8;
            float* d1 = d0 + (size_t)8 * N;
            *(float2*)d0 = make_float2(acc[mt][nt][0], acc[mt][nt][1]);
            *(float2*)d1 = make_float2(acc[mt][nt][2], acc[mt][nt][3]);
        }
}

// ---------------------------------------------------------------------------
// Flash attention, HMMA fp16, causal. Br=128, Bc=64, 256 threads (8 warps).
// (R13-proven, unchanged)
// ---------------------------------------------------------------------------
#define FPITCH 272
#define FTILE (64 * FPITCH)            // K/V tile: 64 rows
#define FQTILE (128 * FPITCH)          // Q tile: 128 rows
#define FLASH_DSMEM (FQTILE + 4 * FTILE)   // 104448

__device__ __forceinline__ void flash_fill_kv(uint32_t sbuf, const __half* src,
                                              int tid) {
#pragma unroll
    for (int i = 0; i < 4; i++) {
        int v = tid + i * 256;          // 0..1023
        int row = v >> 4, c = v & 15;
        cp_async16(sbuf + (uint32_t)row * FPITCH + (uint32_t)c * 16,
                   src + (size_t)row * HD_ + c * 8);
    }
}
__device__ __forceinline__ void flash_fill_q(uint32_t sbuf, const __half* src,
                                             int tid) {
#pragma unroll
    for (int i = 0; i < 8; i++) {
        int v = tid + i * 256;          // 0..2047
        int row = v >> 4, c = v & 15;
        cp_async16(sbuf + (uint32_t)row * FPITCH + (uint32_t)c * 16,
                   src + (size_t)row * HD_ + c * 8);
    }
}

__global__ __launch_bounds__(256, 1)
void flash_hmma_kernel(const __half* __restrict__ Q, const __half* __restrict__ Kg,
                       const __half* __restrict__ Vg, __half* __restrict__ AO) {
    extern __shared__ __align__(128) char dsm[];
    uint32_t sQ = smem_u32(dsm);
    uint32_t sK0 = sQ + FQTILE;
    uint32_t sV0 = sQ + FQTILE + 2 * FTILE;

    int tid = threadIdx.x;
    int w = tid >> 5, l = tid & 31;
    int qt = gridDim.x - 1 - blockIdx.x;   // heavy tiles first
    int bh = blockIdx.y;
    int b = bh / H_, h = bh % H_;
    int kh = h / (H_ / KV_);

    const __half* Qp = Q + ((size_t)(b * H_ + h) * S_ + qt * 128) * HD_;
    const __half* Kp = Kg + ((size_t)(b * KV_ + kh) * S_) * HD_;
    const __half* Vp = Vg + ((size_t)(b * KV_ + kh) * S_) * HD_;

    int ntiles = 2 * qt + 2;

    flash_fill_q(sQ, Qp, tid);
    flash_fill_kv(sK0, Kp, tid);
    flash_fill_kv(sV0, Vp, tid);
    CP_COMMIT();

    uint32_t laneOff = (uint32_t)(l & 15) * FPITCH + (uint32_t)(l >> 4) * 16;

    uint32_t Qf[8][4];
    float O[16][4];
#pragma unroll
    for (int nf = 0; nf < 16; nf++)
#pragma unroll
        for (int i = 0; i < 4; i++) O[nf][i] = 0.f;
    float m0 = -1e30f, m1 = -1e30f, l0 = 0.f, l1 = 0.f;

    int lq = l >> 2;
    int lc2 = (l & 3) * 2;

    for (int j = 0; j < ntiles; j++) {
        int buf = j & 1;
        if (j + 1 < ntiles) {
            int nbuf = (j + 1) & 1;
            flash_fill_kv(sK0 + nbuf * FTILE, Kp + (size_t)(j + 1) * 64 * HD_, tid);
            flash_fill_kv(sV0 + nbuf * FTILE, Vp + (size_t)(j + 1) * 64 * HD_, tid);
            CP_COMMIT();
            cp_wait<1>();
        } else {
            cp_wait<0>();
        }
        __syncthreads();

        if (j == 0) {
            uint32_t qb = sQ + (uint32_t)(w * 16) * FPITCH + laneOff;
#pragma unroll
            for (int kc = 0; kc < 8; kc++) ldsm_x4(Qf[kc], qb + kc * 32);
        }

        // Last diagonal sub-tile is entirely above the diagonal for warps 0-3:
        // skipping is an exact no-op (m,l,O unchanged).
        bool active = !(j == 2 * qt + 1 && w < 4);
        if (active) {
            float sacc[8][4];
#pragma unroll
            for (int nf = 0; nf < 8; nf++)
#pragma unroll
                for (int i = 0; i < 4; i++) sacc[nf][i] = 0.f;

            uint32_t kb = sK0 + (uint32_t)buf * FTILE + laneOff;
#pragma unroll
            for (int kc = 0; kc < 8; kc++) {
#pragma unroll
                for (int g = 0; g < 4; g++) {
                    uint32_t r[4];
                    ldsm_x4(r, kb + (uint32_t)(g * 16) * FPITCH + kc * 32);
                    uint32_t b0[2] = {r[0], r[2]}, b1[2] = {r[1], r[3]};
                    mma16816(sacc[2 * g], Qf[kc], b0);
                    mma16816(sacc[2 * g + 1], Qf[kc], b1);
                }
            }

            if (j >= 2 * qt) {
                int lr0 = qt * 128 + w * 16 + lq, lr1 = lr0 + 8;
                int cb = j * 64;
#pragma unroll
                for (int nf = 0; nf < 8; nf++) {
                    int c0 = cb + nf * 8 + lc2;
                    if (c0 > lr0) sacc[nf][0] = -1e30f;
                    if (c0 + 1 > lr0) sacc[nf][1] = -1e30f;
                    if (c0 > lr1) sacc[nf][2] = -1e30f;
                    if (c0 + 1 > lr1) sacc[nf][3] = -1e30f;
                }
            }

            float mx0 = -1e30f, mx1 = -1e30f;
#pragma unroll
            for (int nf = 0; nf < 8; nf++) {
                mx0 = fmaxf(mx0, fmaxf(sacc[nf][0], sacc[nf][1]));
                mx1 = fmaxf(mx1, fmaxf(sacc[nf][2], sacc[nf][3]));
            }
            mx0 = fmaxf(mx0, __shfl_xor_sync(0xffffffffu, mx0, 1));
            mx0 = fmaxf(mx0, __shfl_xor_sync(0xffffffffu, mx0, 2));
            mx1 = fmaxf(mx1, __shfl_xor_sync(0xffffffffu, mx1, 1));
            mx1 = fmaxf(mx1, __shfl_xor_sync(0xffffffffu, mx1, 2));
            float m0n = fmaxf(m0, mx0), m1n = fmaxf(m1, mx1);
            float f0 = __expf(m0 - m0n), f1 = __expf(m1 - m1n);

            uint32_t Pf[4][4];
            float s0 = 0.f, s1 = 0.f;
#pragma unroll
            for (int kc = 0; kc < 4; kc++) {
                float pa = __expf(sacc[2 * kc][0] - m0n);
                float pb = __expf(sacc[2 * kc][1] - m0n);
                float pc = __expf(sacc[2 * kc][2] - m1n);
                float pd = __expf(sacc[2 * kc][3] - m1n);
                float pe = __expf(sacc[2 * kc + 1][0] - m0n);
                float pf = __expf(sacc[2 * kc + 1][1] - m0n);
                float pg = __expf(sacc[2 * kc + 1][2] - m1n);
                float ph = __expf(sacc[2 * kc + 1][3] - m1n);
                s0 += pa + pb + pe + pf;
                s1 += pc + pd + pg + ph;
                Pf[kc][0] = h2_as_u32(__floats2half2_rn(pa, pb));
                Pf[kc][1] = h2_as_u32(__floats2half2_rn(pc, pd));
                Pf[kc][2] = h2_as_u32(__floats2half2_rn(pe, pf));
                Pf[kc][3] = h2_as_u32(__floats2half2_rn(pg, ph));
            }
            l0 = l0 * f0 + s0;
            l1 = l1 * f1 + s1;
            m0 = m0n; m1 = m1n;

#pragma unroll
            for (int nf = 0; nf < 16; nf++) {
                O[nf][0] *= f0; O[nf][1] *= f0;
                O[nf][2] *= f1; O[nf][3] *= f1;
            }

            uint32_t vb = sV0 + (uint32_t)buf * FTILE + laneOff;
#pragma unroll
            for (int kc = 0; kc < 4; kc++) {
#pragma unroll
                for (int g = 0; g < 8; g++) {
                    uint32_t r[4];
                    ldsm_x4_t(r, vb + (uint32_t)(kc * 16) * FPITCH + g * 32);
                    uint32_t b0[2] = {r[0], r[1]}, b1[2] = {r[2], r[3]};
                    mma16816(O[2 * g], Pf[kc], b0);
                    mma16816(O[2 * g + 1], Pf[kc], b1);
                }
            }
        }
        __syncthreads();
    }

    l0 += __shfl_xor_sync(0xffffffffu, l0, 1);
    l0 += __shfl_xor_sync(0xffffffffu, l0, 2);
    l1 += __shfl_xor_sync(0xffffffffu, l1, 1);
    l1 += __shfl_xor_sync(0xffffffffu, l1, 2);
    float inv0 = 1.0f / l0, inv1 = 1.0f / l1;

    int row0 = qt * 128 + w * 16 + lq;
    __half* base0 = AO + ((size_t)(b * S_ + row0) * H_ + h) * HD_;
    __half* base1 = AO + ((size_t)(b * S_ + row0 + 8) * H_ + h) * HD_;
#pragma unroll
    for (int nf = 0; nf < 16; nf++) {
        int c0 = nf * 8 + lc2;
        *(__half2*)(base0 + c0) = __floats2half2_rn(O[nf][0] * inv0, O[nf][1] * inv0);
        *(__half2*)(base1 + c0) = __floats2half2_rn(O[nf][2] * inv1, O[nf][3] * inv1);
    }
}

// ---------------------------------------------------------------------------
extern "C" void kernel_launch(void* const* d_in, const int* in_sizes, int n_in,
                              void* d_out, int out_size) {
    const float* hs  = (const float*)d_in[0];
    const float* Wq  = (const float*)d_in[1];
    const float* Wk  = (const float*)d_in[2];
    const float* Wv  = (const float*)d_in[3];
    const float* Wo  = (const float*)d_in[4];
    const int*   pos = (const int*)d_in[5];
    float* out = (float*)d_out;

    __half *hsH, *WqH, *WkH, *WvH, *WoH, *QH, *KH, *VH, *AOH;
    cudaGetSymbolAddress((void**)&hsH, g_hsH);
    cudaGetSymbolAddress((void**)&WqH, g_WqH);
    cudaGetSymbolAddress((void**)&WkH, g_WkH);
    cudaGetSymbolAddress((void**)&WvH, g_WvH);
    cudaGetSymbolAddress((void**)&WoH, g_WoH);
    cudaGetSymbolAddress((void**)&QH, g_QH);
    cudaGetSymbolAddress((void**)&KH, g_KH);
    cudaGetSymbolAddress((void**)&VH, g_VH);
    cudaGetSymbolAddress((void**)&AOH, g_AOH);

    cudaFuncSetAttribute(qkv_hmma_kernel,
                         cudaFuncAttributeMaxDynamicSharedMemorySize, GEMM_DSMEM64);
    cudaFuncSetAttribute(gemm_hmma_kernel,
                         cudaFuncAttributeMaxDynamicSharedMemorySize, GEMM_DSMEM64);
    cudaFuncSetAttribute(flash_hmma_kernel,
                         cudaFuncAttributeMaxDynamicSharedMemorySize, FLASH_DSMEM);

    // RoPE tables (needed by qkv epilogue)
    rope_table_kernel<<<(B_ * S_ * 64 + 255) / 256, 256>>>(pos);

    // All fp32 -> fp16 conversions in one launch (MLP=4 per segment)
    convert_all_kernel<<<(CVT_THREADS + 255) / 256, 256>>>(
        hs, Wq, Wk, Wv, Wo, hsH, WqH, WkH, WvH, WoH);

    // Fused QKV projections + RoPE (48 x 64 = 3072 CTAs, 64-row m-tiles)
    qkv_hmma_kernel<<<dim3(48, (B_ * S_) / 64), 256, GEMM_DSMEM64>>>(
        hsH, WqH, WkH, WvH, QH, KH, VH);

    // Flash attention (HMMA, causal, Br=128)
    flash_hmma_kernel<<<dim3(S_ / 128, B_ * H_), 256, FLASH_DSMEM>>>(
        QH, KH, VH, AOH);

    // Output projection (32 x 64 = 2048 CTAs, 64-row m-tiles)
    gemm_hmma_kernel<<<dim3(D_ / 128, (B_ * S_) / 64), 256, GEMM_DSMEM64>>>(
        AOH, WoH, out, B_ * S_, D_, H_ * HD_);
}

// round 16
// speedup vs baseline: 1.2110x; 1.2110x over previous
#include <cuda_runtime.h>
#include <cuda_fp16.h>
#include <math.h>
#include <cstdint>

// Problem constants
#define B_ 2
#define S_ 2048
#define D_ 4096
#define H_ 32
#define KV_ 8
#define HD_ 128

// ---------------------------------------------------------------------------
// Scratch (static __device__ per allocation rules)
// ---------------------------------------------------------------------------
__device__ float g_cos[(size_t)B_ * S_ * 64];
__device__ float g_sin[(size_t)B_ * S_ * 64];
// fp16 tensors
__device__ __half g_hsH[(size_t)B_ * S_ * D_];
__device__ __half g_WqH[(size_t)H_ * HD_ * D_];
__device__ __half g_WkH[(size_t)KV_ * HD_ * D_];
__device__ __half g_WvH[(size_t)KV_ * HD_ * D_];
__device__ __half g_WoH[(size_t)D_ * H_ * HD_];
__device__ __half g_QH[(size_t)B_ * H_ * S_ * HD_];  // roped, pre-scaled
__device__ __half g_KH[(size_t)B_ * KV_ * S_ * HD_]; // roped
__device__ __half g_VH[(size_t)B_ * KV_ * S_ * HD_]; // from GEMM epilogue
__device__ __half g_AOH[(size_t)B_ * S_ * H_ * HD_]; // flash out [B,S,H,HD]

// ---------------------------------------------------------------------------
// Helpers
// ---------------------------------------------------------------------------
__device__ __forceinline__ uint32_t smem_u32(const void* p) {
    uint32_t a;
    asm("{ .reg .u64 t; cvta.to.shared.u64 t, %1; cvt.u32.u64 %0, t; }"
        : "=r"(a) : "l"(p));
    return a;
}
__device__ __forceinline__ uint32_t h2_as_u32(__half2 h) {
    union { __half2 h; uint32_t u; } cvt;
    cvt.h = h;
    return cvt.u;
}
__device__ __forceinline__ void cp_async16(uint32_t saddr, const void* g) {
    asm volatile("cp.async.cg.shared.global [%0], [%1], 16;" :: "r"(saddr), "l"(g));
}
#define CP_COMMIT() asm volatile("cp.async.commit_group;" ::: "memory")
template <int N>
__device__ __forceinline__ void cp_wait() {
    asm volatile("cp.async.wait_group %0;" :: "n"(N) : "memory");
}
__device__ __forceinline__ void ldsm_x4(uint32_t* r, uint32_t addr) {
    asm volatile("ldmatrix.sync.aligned.m8n8.x4.shared.b16 {%0,%1,%2,%3}, [%4];"
                 : "=r"(r[0]), "=r"(r[1]), "=r"(r[2]), "=r"(r[3]) : "r"(addr));
}
__device__ __forceinline__ void ldsm_x4_t(uint32_t* r, uint32_t addr) {
    asm volatile("ldmatrix.sync.aligned.m8n8.x4.trans.shared.b16 {%0,%1,%2,%3}, [%4];"
                 : "=r"(r[0]), "=r"(r[1]), "=r"(r[2]), "=r"(r[3]) : "r"(addr));
}
__device__ __forceinline__ void ldsm_x2(uint32_t* r, uint32_t addr) {
    asm volatile("ldmatrix.sync.aligned.m8n8.x2.shared.b16 {%0,%1}, [%2];"
                 : "=r"(r[0]), "=r"(r[1]) : "r"(addr));
}
__device__ __forceinline__ void mma16816(float* c, const uint32_t* a, const uint32_t* b) {
    asm volatile(
        "mma.sync.aligned.m16n8k16.row.col.f32.f16.f16.f32 "
        "{%0,%1,%2,%3}, {%4,%5,%6,%7}, {%8,%9}, {%0,%1,%2,%3};"
        : "+f"(c[0]), "+f"(c[1]), "+f"(c[2]), "+f"(c[3])
        : "r"(a[0]), "r"(a[1]), "r"(a[2]), "r"(a[3]), "r"(b[0]), "r"(b[1]));
}

// ---------------------------------------------------------------------------
// Merged fp32 -> fp16 conversion for all 5 tensors, MLP=4 per segment.
// Quarter-segment sizes (in float4): hs/Wq/Wo = 1M, Wk/Wv = 256K.
// ---------------------------------------------------------------------------
#define CVT_Q1 (1 << 20)
#define CVT_Q2 (1 << 18)
#define CVT_THREADS (3 * CVT_Q1 + 2 * CVT_Q2)

__global__ void convert_all_kernel(const float* __restrict__ hs,
                                   const float* __restrict__ Wq,
                                   const float* __restrict__ Wk,
                                   const float* __restrict__ Wv,
                                   const float* __restrict__ Wo,
                                   __half* o_hs, __half* o_q, __half* o_k,
                                   __half* o_v, __half* o_o) {
    int gid = blockIdx.x * blockDim.x + threadIdx.x;
    if (gid >= CVT_THREADS) return;
    const float* in;
    __half* out;
    int q, base;
    if (gid < CVT_Q1)            { in = hs; out = o_hs; q = CVT_Q1; base = gid; }
    else if (gid < 2 * CVT_Q1)   { in = Wq; out = o_q;  q = CVT_Q1; base = gid - CVT_Q1; }
    else if (gid < 2 * CVT_Q1 + CVT_Q2)     { in = Wk; out = o_k; q = CVT_Q2; base = gid - 2 * CVT_Q1; }
    else if (gid < 2 * CVT_Q1 + 2 * CVT_Q2) { in = Wv; out = o_v; q = CVT_Q2; base = gid - 2 * CVT_Q1 - CVT_Q2; }
    else                         { in = Wo; out = o_o;  q = CVT_Q1; base = gid - 2 * CVT_Q1 - 2 * CVT_Q2; }
    const float4* in4 = (const float4*)in;
    uint2* o = (uint2*)out;
    float4 a = in4[base];
    float4 b = in4[base + q];
    float4 c = in4[base + 2 * q];
    float4 d = in4[base + 3 * q];
    o[base] = make_uint2(h2_as_u32(__floats2half2_rn(a.x, a.y)),
                         h2_as_u32(__floats2half2_rn(a.z, a.w)));
    o[base + q] = make_uint2(h2_as_u32(__floats2half2_rn(b.x, b.y)),
                             h2_as_u32(__floats2half2_rn(b.z, b.w)));
    o[base + 2 * q] = make_uint2(h2_as_u32(__floats2half2_rn(c.x, c.y)),
                                 h2_as_u32(__floats2half2_rn(c.z, c.w)));
    o[base + 3 * q] = make_uint2(h2_as_u32(__floats2half2_rn(d.x, d.y)),
                                 h2_as_u32(__floats2half2_rn(d.z, d.w)));
}

// ---------------------------------------------------------------------------
// RoPE tables (double-precision angles for accuracy)
// ---------------------------------------------------------------------------
__global__ void rope_table_kernel(const int* __restrict__ pos_ids) {
    int idx = blockIdx.x * blockDim.x + threadIdx.x;
    if (idx >= B_ * S_ * 64) return;
    int i = idx & 63;
    int bs = idx >> 6;
    int p = pos_ids[bs];
    double invf = exp2(-((double)(2 * i) / 128.0) * 13.287712379549449);
    double ang = (double)p * invf;
    double sd, cd;
    sincos(ang, &sd, &cd);
    g_cos[idx] = (float)cd;
    g_sin[idx] = (float)sd;
}

// ---------------------------------------------------------------------------
// HMMA GEMM core (R8/R10/R14-proven): 128x128 tile, BK=32, 4-stage cp.async,
// 256 threads (8 warps, 2x4), warp tile 64x32.
// ---------------------------------------------------------------------------
#define PITCHB 80
#define GSTAGES 4
#define OP_BYTES (128 * PITCHB)
#define STAGE_BYTES (2 * OP_BYTES)
#define GEMM_DSMEM (GSTAGES * STAGE_BYTES)

__device__ __forceinline__ void gemm_fill(uint32_t sA, uint32_t sB,
                                          const __half* A, const __half* Bw,
                                          int m0, int n0, int K, int k0, int tid) {
#pragma unroll
    for (int i = 0; i < 2; i++) {
        int v = tid + i * 256;
        int row = v >> 2, c = v & 3;
        uint32_t off = (uint32_t)row * PITCHB + (uint32_t)c * 16;
        cp_async16(sA + off, A + (size_t)(m0 + row) * K + k0 + c * 8);
        cp_async16(sB + off, Bw + (size_t)(n0 + row) * K + k0 + c * 8);
    }
    CP_COMMIT();
}

// Mainloop producing acc[4][4][4]; caller handles epilogue.
__device__ __forceinline__ void gemm_mainloop(const __half* A, const __half* Bw,
                                              int m0, int n0, int K,
                                              uint32_t sBase, int tid,
                                              float acc[4][4][4]) {
    int wid = tid >> 5, l = tid & 31;
    int warpM = wid >> 2, warpN = wid & 3;
    int KT = K >> 5;

#pragma unroll
    for (int c = 0; c < GSTAGES - 1; c++) {
        uint32_t st = sBase + c * STAGE_BYTES;
        gemm_fill(st, st + OP_BYTES, A, Bw, m0, n0, K, c * 32, tid);
    }

    uint32_t aOff = (uint32_t)(l & 15) * PITCHB + (uint32_t)(l >> 4) * 16;
    uint32_t bOff = (uint32_t)(l & 7) * PITCHB + (uint32_t)((l >> 3) & 1) * 16;

    for (int kt = 0; kt < KT; kt++) {
        if (kt < KT - 2) cp_wait<2>();
        else if (kt == KT - 2) cp_wait<1>();
        else cp_wait<0>();
        __syncthreads();

        int nk = kt + GSTAGES - 1;
        if (nk < KT) {
            uint32_t st = sBase + (uint32_t)(nk % GSTAGES) * STAGE_BYTES;
            gemm_fill(st, st + OP_BYTES, A, Bw, m0, n0, K, nk * 32, tid);
        }

        uint32_t stA = sBase + (uint32_t)(kt % GSTAGES) * STAGE_BYTES;
        uint32_t stB = stA + OP_BYTES;
        uint32_t aBase = stA + (uint32_t)(warpM * 64) * PITCHB + aOff;
        uint32_t bBase = stB + (uint32_t)(warpN * 32) * PITCHB + bOff;

#pragma unroll
        for (int ks = 0; ks < 2; ks++) {
            uint32_t kbyte = ks * 32;
            uint32_t ar[4][4], br[4][2];
#pragma unroll
            for (int mt = 0; mt < 4; mt++)
                ldsm_x4(ar[mt], aBase + (uint32_t)(mt * 16) * PITCHB + kbyte);
#pragma unroll
            for (int nt = 0; nt < 4; nt++)
                ldsm_x2(br[nt], bBase + (uint32_t)(nt * 8) * PITCHB + kbyte);
#pragma unroll
            for (int mt = 0; mt < 4; mt++)
#pragma unroll
                for (int nt = 0; nt < 4; nt++)
                    mma16816(acc[mt][nt], ar[mt], br[nt]);
        }
    }
}

// Fused QKV projection + RoPE. blockIdx.x in [0,48):
//   [0,32)  : Wq -> QH (rope + 1/sqrt(HD) scale, fp16)
//   [32,40) : Wk -> KH (rope, fp16)
//   [40,48) : Wv -> VH (fp16)
__global__ __launch_bounds__(256, 2)
void qkv_hmma_kernel(const __half* __restrict__ A,
                     const __half* __restrict__ Wq, const __half* __restrict__ Wk,
                     const __half* __restrict__ Wv,
                     __half* __restrict__ Qo, __half* __restrict__ Ko,
                     __half* __restrict__ Vo) {
    extern __shared__ __align__(128) char dsm[];
    uint32_t sBase = smem_u32(dsm);
    int tid = threadIdx.x;
    int bx = blockIdx.x;
    int m0 = blockIdx.y * 128;

    const __half* Bw;
    int head;
    int seg;                         // 0=Q, 1=K, 2=V
    if (bx < 32)      { Bw = Wq; head = bx;      seg = 0; }
    else if (bx < 40) { Bw = Wk; head = bx - 32; seg = 1; }
    else              { Bw = Wv; head = bx - 40; seg = 2; }
    int n0 = head * 128;
    int NH = (seg == 0) ? H_ : KV_;

    float acc[4][4][4];
#pragma unroll
    for (int mt = 0; mt < 4; mt++)
#pragma unroll
        for (int nt = 0; nt < 4; nt++)
#pragma unroll
            for (int i = 0; i < 4; i++) acc[mt][nt][i] = 0.f;

    gemm_mainloop(A, Bw, m0, n0, D_, sBase, tid, acc);

    int wid = tid >> 5, l = tid & 31;
    int warpM = wid >> 2, warpN = wid & 3;
    int rl0 = warpM * 64 + (l >> 2);
    int cl0 = warpN * 32 + (l & 3) * 2;
    int b = m0 / S_;
    int srow = m0 % S_;

    if (seg == 2) {
        __half* Cb = Vo + ((size_t)(b * NH + head) * S_ + srow) * HD_;
#pragma unroll
        for (int mt = 0; mt < 4; mt++)
#pragma unroll
            for (int nt = 0; nt < 4; nt++) {
                __half* d0 = Cb + (size_t)(rl0 + mt * 16) * HD_ + cl0 + nt * 8;
                __half* d1 = d0 + (size_t)8 * HD_;
                *(__half2*)d0 = __floats2half2_rn(acc[mt][nt][0], acc[mt][nt][1]);
                *(__half2*)d1 = __floats2half2_rn(acc[mt][nt][2], acc[mt][nt][3]);
            }
        return;
    }

    // ---- Q/K: stage fp32 tile in smem, apply RoPE, write fp16 ----
    __syncthreads();                 // mainloop smem no longer needed
    float* tileS = (float*)dsm;      // 128 x 128, pitch 132 floats (67584 B)
#pragma unroll
    for (int mt = 0; mt < 4; mt++)
#pragma unroll
        for (int nt = 0; nt < 4; nt++) {
            int r0 = rl0 + mt * 16;
            int c0 = cl0 + nt * 8;
            tileS[r0 * 132 + c0]       = acc[mt][nt][0];
            tileS[r0 * 132 + c0 + 1]   = acc[mt][nt][1];
            tileS[(r0 + 8) * 132 + c0]     = acc[mt][nt][2];
            tileS[(r0 + 8) * 132 + c0 + 1] = acc[mt][nt][3];
        }
    __syncthreads();

    __half* outp = ((seg == 0) ? Qo : Ko) +
                   ((size_t)(b * NH + head) * S_ + srow) * HD_;
    float scl = (seg == 0) ? 0.08838834764831845f : 1.0f;
    int c4 = (tid & 15) * 4;         // pair-col base (0..60)
    int rb = tid >> 4;               // 0..15
#pragma unroll
    for (int it = 0; it < 8; it++) {
        int r = rb + it * 16;
        int s = srow + r;
        float4 x1 = *(float4*)&tileS[r * 132 + c4];
        float4 x2 = *(float4*)&tileS[r * 132 + c4 + 64];
        int ti = (b * S_ + s) * 64 + c4;
        float4 cs = *(float4*)&g_cos[ti];
        float4 sn = *(float4*)&g_sin[ti];
        float o0x = (x1.x * cs.x - x2.x * sn.x) * scl;
        float o0y = (x1.y * cs.y - x2.y * sn.y) * scl;
        float o0z = (x1.z * cs.z - x2.z * sn.z) * scl;
        float o0w = (x1.w * cs.w - x2.w * sn.w) * scl;
        float o1x = (x2.x * cs.x + x1.x * sn.x) * scl;
        float o1y = (x2.y * cs.y + x1.y * sn.y) * scl;
        float o1z = (x2.z * cs.z + x1.z * sn.z) * scl;
        float o1w = (x2.w * cs.w + x1.w * sn.w) * scl;
        __half2 lo0 = __floats2half2_rn(o0x, o0y);
        __half2 lo1 = __floats2half2_rn(o0z, o0w);
        __half2 hi0 = __floats2half2_rn(o1x, o1y);
        __half2 hi1 = __floats2half2_rn(o1z, o1w);
        uint2 pk0 = make_uint2(h2_as_u32(lo0), h2_as_u32(lo1));
        uint2 pk1 = make_uint2(h2_as_u32(hi0), h2_as_u32(hi1));
        *(uint2*)&outp[(size_t)r * HD_ + c4]      = pk0;
        *(uint2*)&outp[(size_t)r * HD_ + c4 + 64] = pk1;
    }
}

// Plain GEMM (O projection): C fp32 row-major [M,N].
__global__ __launch_bounds__(256, 2)
void gemm_hmma_kernel(const __half* __restrict__ A, const __half* __restrict__ Bw,
                      float* __restrict__ C, int M, int N, int K) {
    extern __shared__ __align__(128) char dsm[];
    uint32_t sBase = smem_u32(dsm);
    int tid = threadIdx.x;
    int m0 = blockIdx.y * 128, n0 = blockIdx.x * 128;

    float acc[4][4][4];
#pragma unroll
    for (int mt = 0; mt < 4; mt++)
#pragma unroll
        for (int nt = 0; nt < 4; nt++)
#pragma unroll
            for (int i = 0; i < 4; i++) acc[mt][nt][i] = 0.f;

    gemm_mainloop(A, Bw, m0, n0, K, sBase, tid, acc);

    int wid = tid >> 5, l = tid & 31;
    int warpM = wid >> 2, warpN = wid & 3;
    int rl0 = warpM * 64 + (l >> 2);
    int cl0 = warpN * 32 + (l & 3) * 2;
    float* Cb = C + (size_t)m0 * N + n0;
#pragma unroll
    for (int mt = 0; mt < 4; mt++)
#pragma unroll
        for (int nt = 0; nt < 4; nt++) {
            float* d0 = Cb + (size_t)(rl0 + mt * 16) * N + cl0 + nt * 8;
            float* d1 = d0 + (size_t)8 * N;
            *(float2*)d0 = make_float2(acc[mt][nt][0], acc[mt][nt][1]);
            *(float2*)d1 = make_float2(acc[mt][nt][2], acc[mt][nt][3]);
        }
}

// ---------------------------------------------------------------------------
// Flash attention, HMMA fp16, causal. Br=128, Bc=64, 256 threads (8 warps).
// (R13/R14-proven, unchanged)
// ---------------------------------------------------------------------------
#define FPITCH 272
#define FTILE (64 * FPITCH)            // K/V tile: 64 rows
#define FQTILE (128 * FPITCH)          // Q tile: 128 rows
#define FLASH_DSMEM (FQTILE + 4 * FTILE)   // 104448

__device__ __forceinline__ void flash_fill_kv(uint32_t sbuf, const __half* src,
                                              int tid) {
#pragma unroll
    for (int i = 0; i < 4; i++) {
        int v = tid + i * 256;          // 0..1023
        int row = v >> 4, c = v & 15;
        cp_async16(sbuf + (uint32_t)row * FPITCH + (uint32_t)c * 16,
                   src + (size_t)row * HD_ + c * 8);
    }
}
__device__ __forceinline__ void flash_fill_q(uint32_t sbuf, const __half* src,
                                             int tid) {
#pragma unroll
    for (int i = 0; i < 8; i++) {
        int v = tid + i * 256;          // 0..2047
        int row = v >> 4, c = v & 15;
        cp_async16(sbuf + (uint32_t)row * FPITCH + (uint32_t)c * 16,
                   src + (size_t)row * HD_ + c * 8);
    }
}

__global__ __launch_bounds__(256, 1)
void flash_hmma_kernel(const __half* __restrict__ Q, const __half* __restrict__ Kg,
                       const __half* __restrict__ Vg, __half* __restrict__ AO) {
    extern __shared__ __align__(128) char dsm[];
    uint32_t sQ = smem_u32(dsm);
    uint32_t sK0 = sQ + FQTILE;
    uint32_t sV0 = sQ + FQTILE + 2 * FTILE;

    int tid = threadIdx.x;
    int w = tid >> 5, l = tid & 31;
    int qt = gridDim.x - 1 - blockIdx.x;   // heavy tiles first
    int bh = blockIdx.y;
    int b = bh / H_, h = bh % H_;
    int kh = h / (H_ / KV_);

    const __half* Qp = Q + ((size_t)(b * H_ + h) * S_ + qt * 128) * HD_;
    const __half* Kp = Kg + ((size_t)(b * KV_ + kh) * S_) * HD_;
    const __half* Vp = Vg + ((size_t)(b * KV_ + kh) * S_) * HD_;

    int ntiles = 2 * qt + 2;

    flash_fill_q(sQ, Qp, tid);
    flash_fill_kv(sK0, Kp, tid);
    flash_fill_kv(sV0, Vp, tid);
    CP_COMMIT();

    uint32_t laneOff = (uint32_t)(l & 15) * FPITCH + (uint32_t)(l >> 4) * 16;

    uint32_t Qf[8][4];
    float O[16][4];
#pragma unroll
    for (int nf = 0; nf < 16; nf++)
#pragma unroll
        for (int i = 0; i < 4; i++) O[nf][i] = 0.f;
    float m0 = -1e30f, m1 = -1e30f, l0 = 0.f, l1 = 0.f;

    int lq = l >> 2;
    int lc2 = (l & 3) * 2;

    for (int j = 0; j < ntiles; j++) {
        int buf = j & 1;
        if (j + 1 < ntiles) {
            int nbuf = (j + 1) & 1;
            flash_fill_kv(sK0 + nbuf * FTILE, Kp + (size_t)(j + 1) * 64 * HD_, tid);
            flash_fill_kv(sV0 + nbuf * FTILE, Vp + (size_t)(j + 1) * 64 * HD_, tid);
            CP_COMMIT();
            cp_wait<1>();
        } else {
            cp_wait<0>();
        }
        __syncthreads();

        if (j == 0) {
            uint32_t qb = sQ + (uint32_t)(w * 16) * FPITCH + laneOff;
#pragma unroll
            for (int kc = 0; kc < 8; kc++) ldsm_x4(Qf[kc], qb + kc * 32);
        }

        // Last diagonal sub-tile is entirely above the diagonal for warps 0-3:
        // skipping is an exact no-op (m,l,O unchanged).
        bool active = !(j == 2 * qt + 1 && w < 4);
        if (active) {
            float sacc[8][4];
#pragma unroll
            for (int nf = 0; nf < 8; nf++)
#pragma unroll
                for (int i = 0; i < 4; i++) sacc[nf][i] = 0.f;

            uint32_t kb = sK0 + (uint32_t)buf * FTILE + laneOff;
#pragma unroll
            for (int kc = 0; kc < 8; kc++) {
#pragma unroll
                for (int g = 0; g < 4; g++) {
                    uint32_t r[4];
                    ldsm_x4(r, kb + (uint32_t)(g * 16) * FPITCH + kc * 32);
                    uint32_t b0[2] = {r[0], r[2]}, b1[2] = {r[1], r[3]};
                    mma16816(sacc[2 * g], Qf[kc], b0);
                    mma16816(sacc[2 * g + 1], Qf[kc], b1);
                }
            }

            if (j >= 2 * qt) {
                int lr0 = qt * 128 + w * 16 + lq, lr1 = lr0 + 8;
                int cb = j * 64;
#pragma unroll
                for (int nf = 0; nf < 8; nf++) {
                    int c0 = cb + nf * 8 + lc2;
                    if (c0 > lr0) sacc[nf][0] = -1e30f;
                    if (c0 + 1 > lr0) sacc[nf][1] = -1e30f;
                    if (c0 > lr1) sacc[nf][2] = -1e30f;
                    if (c0 + 1 > lr1) sacc[nf][3] = -1e30f;
                }
            }

            float mx0 = -1e30f, mx1 = -1e30f;
#pragma unroll
            for (int nf = 0; nf < 8; nf++) {
                mx0 = fmaxf(mx0, fmaxf(sacc[nf][0], sacc[nf][1]));
                mx1 = fmaxf(mx1, fmaxf(sacc[nf][2], sacc[nf][3]));
            }
            mx0 = fmaxf(mx0, __shfl_xor_sync(0xffffffffu, mx0, 1));
            mx0 = fmaxf(mx0, __shfl_xor_sync(0xffffffffu, mx0, 2));
            mx1 = fmaxf(mx1, __shfl_xor_sync(0xffffffffu, mx1, 1));
            mx1 = fmaxf(mx1, __shfl_xor_sync(0xffffffffu, mx1, 2));
            float m0n = fmaxf(m0, mx0), m1n = fmaxf(m1, mx1);
            float f0 = __expf(m0 - m0n), f1 = __expf(m1 - m1n);

            uint32_t Pf[4][4];
            float s0 = 0.f, s1 = 0.f;
#pragma unroll
            for (int kc = 0; kc < 4; kc++) {
                float pa = __expf(sacc[2 * kc][0] - m0n);
                float pb = __expf(sacc[2 * kc][1] - m0n);
                float pc = __expf(sacc[2 * kc][2] - m1n);
                float pd = __expf(sacc[2 * kc][3] - m1n);
                float pe = __expf(sacc[2 * kc + 1][0] - m0n);
                float pf = __expf(sacc[2 * kc + 1][1] - m0n);
                float pg = __expf(sacc[2 * kc + 1][2] - m1n);
                float ph = __expf(sacc[2 * kc + 1][3] - m1n);
                s0 += pa + pb + pe + pf;
                s1 += pc + pd + pg + ph;
                Pf[kc][0] = h2_as_u32(__floats2half2_rn(pa, pb));
                Pf[kc][1] = h2_as_u32(__floats2half2_rn(pc, pd));
                Pf[kc][2] = h2_as_u32(__floats2half2_rn(pe, pf));
                Pf[kc][3] = h2_as_u32(__floats2half2_rn(pg, ph));
            }
            l0 = l0 * f0 + s0;
            l1 = l1 * f1 + s1;
            m0 = m0n; m1 = m1n;

#pragma unroll
            for (int nf = 0; nf < 16; nf++) {
                O[nf][0] *= f0; O[nf][1] *= f0;
                O[nf][2] *= f1; O[nf][3] *= f1;
            }

            uint32_t vb = sV0 + (uint32_t)buf * FTILE + laneOff;
#pragma unroll
            for (int kc = 0; kc < 4; kc++) {
#pragma unroll
                for (int g = 0; g < 8; g++) {
                    uint32_t r[4];
                    ldsm_x4_t(r, vb + (uint32_t)(kc * 16) * FPITCH + g * 32);
                    uint32_t b0[2] = {r[0], r[1]}, b1[2] = {r[2], r[3]};
                    mma16816(O[2 * g], Pf[kc], b0);
                    mma16816(O[2 * g + 1], Pf[kc], b1);
                }
            }
        }
        __syncthreads();
    }

    l0 += __shfl_xor_sync(0xffffffffu, l0, 1);
    l0 += __shfl_xor_sync(0xffffffffu, l0, 2);
    l1 += __shfl_xor_sync(0xffffffffu, l1, 1);
    l1 += __shfl_xor_sync(0xffffffffu, l1, 2);
    float inv0 = 1.0f / l0, inv1 = 1.0f / l1;

    int row0 = qt * 128 + w * 16 + lq;
    __half* base0 = AO + ((size_t)(b * S_ + row0) * H_ + h) * HD_;
    __half* base1 = AO + ((size_t)(b * S_ + row0 + 8) * H_ + h) * HD_;
#pragma unroll
    for (int nf = 0; nf < 16; nf++) {
        int c0 = nf * 8 + lc2;
        *(__half2*)(base0 + c0) = __floats2half2_rn(O[nf][0] * inv0, O[nf][1] * inv0);
        *(__half2*)(base1 + c0) = __floats2half2_rn(O[nf][2] * inv1, O[nf][3] * inv1);
    }
}

// ---------------------------------------------------------------------------
extern "C" void kernel_launch(void* const* d_in, const int* in_sizes, int n_in,
                              void* d_out, int out_size) {
    const float* hs  = (const float*)d_in[0];
    const float* Wq  = (const float*)d_in[1];
    const float* Wk  = (const float*)d_in[2];
    const float* Wv  = (const float*)d_in[3];
    const float* Wo  = (const float*)d_in[4];
    const int*   pos = (const int*)d_in[5];
    float* out = (float*)d_out;

    __half *hsH, *WqH, *WkH, *WvH, *WoH, *QH, *KH, *VH, *AOH;
    cudaGetSymbolAddress((void**)&hsH, g_hsH);
    cudaGetSymbolAddress((void**)&WqH, g_WqH);
    cudaGetSymbolAddress((void**)&WkH, g_WkH);
    cudaGetSymbolAddress((void**)&WvH, g_WvH);
    cudaGetSymbolAddress((void**)&WoH, g_WoH);
    cudaGetSymbolAddress((void**)&QH, g_QH);
    cudaGetSymbolAddress((void**)&KH, g_KH);
    cudaGetSymbolAddress((void**)&VH, g_VH);
    cudaGetSymbolAddress((void**)&AOH, g_AOH);

    cudaFuncSetAttribute(qkv_hmma_kernel,
                         cudaFuncAttributeMaxDynamicSharedMemorySize, GEMM_DSMEM);
    cudaFuncSetAttribute(gemm_hmma_kernel,
                         cudaFuncAttributeMaxDynamicSharedMemorySize, GEMM_DSMEM);
    cudaFuncSetAttribute(flash_hmma_kernel,
                         cudaFuncAttributeMaxDynamicSharedMemorySize, FLASH_DSMEM);

    // RoPE tables (needed by qkv epilogue)
    rope_table_kernel<<<(B_ * S_ * 64 + 255) / 256, 256>>>(pos);

    // All fp32 -> fp16 conversions in one launch (MLP=4 per segment)
    convert_all_kernel<<<(CVT_THREADS + 255) / 256, 256>>>(
        hs, Wq, Wk, Wv, Wo, hsH, WqH, WkH, WvH, WoH);

    // Fused QKV projections + RoPE (48 x 32 = 1536 CTAs, 128-row m-tiles)
    qkv_hmma_kernel<<<dim3(48, (B_ * S_) / 128), 256, GEMM_DSMEM>>>(
        hsH, WqH, WkH, WvH, QH, KH, VH);

    // Flash attention (HMMA, causal, Br=128)
    flash_hmma_kernel<<<dim3(S_ / 128, B_ * H_), 256, FLASH_DSMEM>>>(
        QH, KH, VH, AOH);

    // Output projection (32 x 32 = 1024 CTAs, 128-row m-tiles)
    gemm_hmma_kernel<<<dim3(D_ / 128, (B_ * S_) / 128), 256, GEMM_DSMEM>>>(
        AOH, WoH, out, B_ * S_, D_, H_ * HD_);
}

// round 17
// speedup vs baseline: 1.3392x; 1.1059x over previous
#include <cuda_runtime.h>
#include <cuda_fp16.h>
#include <math.h>
#include <cstdint>

// Problem constants
#define B_ 2
#define S_ 2048
#define D_ 4096
#define H_ 32
#define KV_ 8
#define HD_ 128

// ---------------------------------------------------------------------------
// Scratch (static __device__ per allocation rules)
// ---------------------------------------------------------------------------
__device__ float g_cos[(size_t)B_ * S_ * 64];
__device__ float g_sin[(size_t)B_ * S_ * 64];
// fp16 tensors
__device__ __half g_hsH[(size_t)B_ * S_ * D_];
__device__ __half g_WqH[(size_t)H_ * HD_ * D_];
__device__ __half g_WkH[(size_t)KV_ * HD_ * D_];
__device__ __half g_WvH[(size_t)KV_ * HD_ * D_];
__device__ __half g_WoH[(size_t)D_ * H_ * HD_];
__device__ __half g_QH[(size_t)B_ * H_ * S_ * HD_];  // roped, pre-scaled
__device__ __half g_KH[(size_t)B_ * KV_ * S_ * HD_]; // roped
__device__ __half g_VH[(size_t)B_ * KV_ * S_ * HD_]; // from GEMM epilogue
__device__ __half g_AOH[(size_t)B_ * S_ * H_ * HD_]; // flash out [B,S,H,HD]

// ---------------------------------------------------------------------------
// Helpers
// ---------------------------------------------------------------------------
__device__ __forceinline__ uint32_t smem_u32(const void* p) {
    uint32_t a;
    asm("{ .reg .u64 t; cvta.to.shared.u64 t, %1; cvt.u32.u64 %0, t; }"
        : "=r"(a) : "l"(p));
    return a;
}
__device__ __forceinline__ uint32_t h2_as_u32(__half2 h) {
    union { __half2 h; uint32_t u; } cvt;
    cvt.h = h;
    return cvt.u;
}
__device__ __forceinline__ void cp_async16(uint32_t saddr, const void* g) {
    asm volatile("cp.async.cg.shared.global [%0], [%1], 16;" :: "r"(saddr), "l"(g));
}
#define CP_COMMIT() asm volatile("cp.async.commit_group;" ::: "memory")
template <int N>
__device__ __forceinline__ void cp_wait() {
    asm volatile("cp.async.wait_group %0;" :: "n"(N) : "memory");
}
__device__ __forceinline__ void ldsm_x4(uint32_t* r, uint32_t addr) {
    asm volatile("ldmatrix.sync.aligned.m8n8.x4.shared.b16 {%0,%1,%2,%3}, [%4];"
                 : "=r"(r[0]), "=r"(r[1]), "=r"(r[2]), "=r"(r[3]) : "r"(addr));
}
__device__ __forceinline__ void ldsm_x4_t(uint32_t* r, uint32_t addr) {
    asm volatile("ldmatrix.sync.aligned.m8n8.x4.trans.shared.b16 {%0,%1,%2,%3}, [%4];"
                 : "=r"(r[0]), "=r"(r[1]), "=r"(r[2]), "=r"(r[3]) : "r"(addr));
}
__device__ __forceinline__ void ldsm_x2(uint32_t* r, uint32_t addr) {
    asm volatile("ldmatrix.sync.aligned.m8n8.x2.shared.b16 {%0,%1}, [%2];"
                 : "=r"(r[0]), "=r"(r[1]) : "r"(addr));
}
__device__ __forceinline__ void mma16816(float* c, const uint32_t* a, const uint32_t* b) {
    asm volatile(
        "mma.sync.aligned.m16n8k16.row.col.f32.f16.f16.f32 "
        "{%0,%1,%2,%3}, {%4,%5,%6,%7}, {%8,%9}, {%0,%1,%2,%3};"
        : "+f"(c[0]), "+f"(c[1]), "+f"(c[2]), "+f"(c[3])
        : "r"(a[0]), "r"(a[1]), "r"(a[2]), "r"(a[3]), "r"(b[0]), "r"(b[1]));
}

// ---------------------------------------------------------------------------
// Merged fp32 -> fp16 conversion for all 5 tensors, MLP=4 per segment.
// ---------------------------------------------------------------------------
#define CVT_Q1 (1 << 20)
#define CVT_Q2 (1 << 18)
#define CVT_THREADS (3 * CVT_Q1 + 2 * CVT_Q2)

__global__ void convert_all_kernel(const float* __restrict__ hs,
                                   const float* __restrict__ Wq,
                                   const float* __restrict__ Wk,
                                   const float* __restrict__ Wv,
                                   const float* __restrict__ Wo,
                                   __half* o_hs, __half* o_q, __half* o_k,
                                   __half* o_v, __half* o_o) {
    int gid = blockIdx.x * blockDim.x + threadIdx.x;
    if (gid >= CVT_THREADS) return;
    const float* in;
    __half* out;
    int q, base;
    if (gid < CVT_Q1)            { in = hs; out = o_hs; q = CVT_Q1; base = gid; }
    else if (gid < 2 * CVT_Q1)   { in = Wq; out = o_q;  q = CVT_Q1; base = gid - CVT_Q1; }
    else if (gid < 2 * CVT_Q1 + CVT_Q2)     { in = Wk; out = o_k; q = CVT_Q2; base = gid - 2 * CVT_Q1; }
    else if (gid < 2 * CVT_Q1 + 2 * CVT_Q2) { in = Wv; out = o_v; q = CVT_Q2; base = gid - 2 * CVT_Q1 - CVT_Q2; }
    else                         { in = Wo; out = o_o;  q = CVT_Q1; base = gid - 2 * CVT_Q1 - 2 * CVT_Q2; }
    const float4* in4 = (const float4*)in;
    uint2* o = (uint2*)out;
    float4 a = in4[base];
    float4 b = in4[base + q];
    float4 c = in4[base + 2 * q];
    float4 d = in4[base + 3 * q];
    o[base] = make_uint2(h2_as_u32(__floats2half2_rn(a.x, a.y)),
                         h2_as_u32(__floats2half2_rn(a.z, a.w)));
    o[base + q] = make_uint2(h2_as_u32(__floats2half2_rn(b.x, b.y)),
                             h2_as_u32(__floats2half2_rn(b.z, b.w)));
    o[base + 2 * q] = make_uint2(h2_as_u32(__floats2half2_rn(c.x, c.y)),
                                 h2_as_u32(__floats2half2_rn(c.z, c.w)));
    o[base + 3 * q] = make_uint2(h2_as_u32(__floats2half2_rn(d.x, d.y)),
                                 h2_as_u32(__floats2half2_rn(d.z, d.w)));
}

// ---------------------------------------------------------------------------
// RoPE tables (double-precision angles for accuracy)
// ---------------------------------------------------------------------------
__global__ void rope_table_kernel(const int* __restrict__ pos_ids) {
    int idx = blockIdx.x * blockDim.x + threadIdx.x;
    if (idx >= B_ * S_ * 64) return;
    int i = idx & 63;
    int bs = idx >> 6;
    int p = pos_ids[bs];
    double invf = exp2(-((double)(2 * i) / 128.0) * 13.287712379549449);
    double ang = (double)p * invf;
    double sd, cd;
    sincos(ang, &sd, &cd);
    g_cos[idx] = (float)cd;
    g_sin[idx] = (float)sd;
}

// ---------------------------------------------------------------------------
// HMMA GEMM core: 128x128 tile, BK=64, 3-stage cp.async, 256 threads
// (8 warps, 2x4), warp tile 64x32. Pitch 144B (9*16B): 9r mod 8 = r mod 8
// -> conflict-free ldmatrix. Same ascending-k MMA order per accumulator as
// the BK=32 version -> bit-identical results; half the syncthreads.
// ---------------------------------------------------------------------------
#define GP 144
#define GSTAGES 3
#define OP_BYTES (128 * GP)              // 18432
#define STAGE_BYTES (2 * OP_BYTES)       // 36864
#define GEMM_DSMEM (GSTAGES * STAGE_BYTES) // 110592

__device__ __forceinline__ void gemm_fill(uint32_t sA, uint32_t sB,
                                          const __half* A, const __half* Bw,
                                          int m0, int n0, int K, int k0, int tid) {
#pragma unroll
    for (int i = 0; i < 4; i++) {
        int v = tid + i * 256;           // 0..1023
        int row = v >> 3, c = v & 7;
        uint32_t off = (uint32_t)row * GP + (uint32_t)c * 16;
        cp_async16(sA + off, A + (size_t)(m0 + row) * K + k0 + c * 8);
        cp_async16(sB + off, Bw + (size_t)(n0 + row) * K + k0 + c * 8);
    }
    CP_COMMIT();
}

// Mainloop producing acc[4][4][4]; caller handles epilogue.
__device__ __forceinline__ void gemm_mainloop(const __half* A, const __half* Bw,
                                              int m0, int n0, int K,
                                              uint32_t sBase, int tid,
                                              float acc[4][4][4]) {
    int wid = tid >> 5, l = tid & 31;
    int warpM = wid >> 2, warpN = wid & 3;
    int KT = K >> 6;                     // 64-wide chunks

    // prologue: stages 0,1
    gemm_fill(sBase, sBase + OP_BYTES, A, Bw, m0, n0, K, 0, tid);
    gemm_fill(sBase + STAGE_BYTES, sBase + STAGE_BYTES + OP_BYTES,
              A, Bw, m0, n0, K, 64, tid);

    uint32_t aOff = (uint32_t)(l & 15) * GP + (uint32_t)(l >> 4) * 16;
    uint32_t bOff = (uint32_t)(l & 7) * GP + (uint32_t)((l >> 3) & 1) * 16;

    for (int kt = 0; kt < KT; kt++) {
        if (kt < KT - 1) cp_wait<1>();
        else cp_wait<0>();
        __syncthreads();

        int nk = kt + 2;
        if (nk < KT) {
            uint32_t st = sBase + (uint32_t)(nk % GSTAGES) * STAGE_BYTES;
            gemm_fill(st, st + OP_BYTES, A, Bw, m0, n0, K, nk * 64, tid);
        }

        uint32_t stA = sBase + (uint32_t)(kt % GSTAGES) * STAGE_BYTES;
        uint32_t stB = stA + OP_BYTES;
        uint32_t aBase = stA + (uint32_t)(warpM * 64) * GP + aOff;
        uint32_t bBase = stB + (uint32_t)(warpN * 32) * GP + bOff;

#pragma unroll
        for (int ks = 0; ks < 4; ks++) {
            uint32_t kbyte = ks * 32;
            uint32_t ar[4][4], br[4][2];
#pragma unroll
            for (int mt = 0; mt < 4; mt++)
                ldsm_x4(ar[mt], aBase + (uint32_t)(mt * 16) * GP + kbyte);
#pragma unroll
            for (int nt = 0; nt < 4; nt++)
                ldsm_x2(br[nt], bBase + (uint32_t)(nt * 8) * GP + kbyte);
#pragma unroll
            for (int mt = 0; mt < 4; mt++)
#pragma unroll
                for (int nt = 0; nt < 4; nt++)
                    mma16816(acc[mt][nt], ar[mt], br[nt]);
        }
    }
}

// Fused QKV projection + RoPE. blockIdx.x in [0,48):
//   [0,32)  : Wq -> QH (rope + 1/sqrt(HD) scale, fp16)
//   [32,40) : Wk -> KH (rope, fp16)
//   [40,48) : Wv -> VH (fp16)
__global__ __launch_bounds__(256, 2)
void qkv_hmma_kernel(const __half* __restrict__ A,
                     const __half* __restrict__ Wq, const __half* __restrict__ Wk,
                     const __half* __restrict__ Wv,
                     __half* __restrict__ Qo, __half* __restrict__ Ko,
                     __half* __restrict__ Vo) {
    extern __shared__ __align__(128) char dsm[];
    uint32_t sBase = smem_u32(dsm);
    int tid = threadIdx.x;
    int bx = blockIdx.x;
    int m0 = blockIdx.y * 128;

    const __half* Bw;
    int head;
    int seg;                         // 0=Q, 1=K, 2=V
    if (bx < 32)      { Bw = Wq; head = bx;      seg = 0; }
    else if (bx < 40) { Bw = Wk; head = bx - 32; seg = 1; }
    else              { Bw = Wv; head = bx - 40; seg = 2; }
    int n0 = head * 128;
    int NH = (seg == 0) ? H_ : KV_;

    float acc[4][4][4];
#pragma unroll
    for (int mt = 0; mt < 4; mt++)
#pragma unroll
        for (int nt = 0; nt < 4; nt++)
#pragma unroll
            for (int i = 0; i < 4; i++) acc[mt][nt][i] = 0.f;

    gemm_mainloop(A, Bw, m0, n0, D_, sBase, tid, acc);

    int wid = tid >> 5, l = tid & 31;
    int warpM = wid >> 2, warpN = wid & 3;
    int rl0 = warpM * 64 + (l >> 2);
    int cl0 = warpN * 32 + (l & 3) * 2;
    int b = m0 / S_;
    int srow = m0 % S_;

    if (seg == 2) {
        __half* Cb = Vo + ((size_t)(b * NH + head) * S_ + srow) * HD_;
#pragma unroll
        for (int mt = 0; mt < 4; mt++)
#pragma unroll
            for (int nt = 0; nt < 4; nt++) {
                __half* d0 = Cb + (size_t)(rl0 + mt * 16) * HD_ + cl0 + nt * 8;
                __half* d1 = d0 + (size_t)8 * HD_;
                *(__half2*)d0 = __floats2half2_rn(acc[mt][nt][0], acc[mt][nt][1]);
                *(__half2*)d1 = __floats2half2_rn(acc[mt][nt][2], acc[mt][nt][3]);
            }
        return;
    }

    // ---- Q/K: stage fp32 tile in smem, apply RoPE, write fp16 ----
    __syncthreads();                 // mainloop smem no longer needed
    float* tileS = (float*)dsm;      // 128 x 128, pitch 132 floats (67584 B)
#pragma unroll
    for (int mt = 0; mt < 4; mt++)
#pragma unroll
        for (int nt = 0; nt < 4; nt++) {
            int r0 = rl0 + mt * 16;
            int c0 = cl0 + nt * 8;
            tileS[r0 * 132 + c0]       = acc[mt][nt][0];
            tileS[r0 * 132 + c0 + 1]   = acc[mt][nt][1];
            tileS[(r0 + 8) * 132 + c0]     = acc[mt][nt][2];
            tileS[(r0 + 8) * 132 + c0 + 1] = acc[mt][nt][3];
        }
    __syncthreads();

    __half* outp = ((seg == 0) ? Qo : Ko) +
                   ((size_t)(b * NH + head) * S_ + srow) * HD_;
    float scl = (seg == 0) ? 0.08838834764831845f : 1.0f;
    int c4 = (tid & 15) * 4;         // pair-col base (0..60)
    int rb = tid >> 4;               // 0..15
#pragma unroll
    for (int it = 0; it < 8; it++) {
        int r = rb + it * 16;
        int s = srow + r;
        float4 x1 = *(float4*)&tileS[r * 132 + c4];
        float4 x2 = *(float4*)&tileS[r * 132 + c4 + 64];
        int ti = (b * S_ + s) * 64 + c4;
        float4 cs = *(float4*)&g_cos[ti];
        float4 sn = *(float4*)&g_sin[ti];
        float o0x = (x1.x * cs.x - x2.x * sn.x) * scl;
        float o0y = (x1.y * cs.y - x2.y * sn.y) * scl;
        float o0z = (x1.z * cs.z - x2.z * sn.z) * scl;
        float o0w = (x1.w * cs.w - x2.w * sn.w) * scl;
        float o1x = (x2.x * cs.x + x1.x * sn.x) * scl;
        float o1y = (x2.y * cs.y + x1.y * sn.y) * scl;
        float o1z = (x2.z * cs.z + x1.z * sn.z) * scl;
        float o1w = (x2.w * cs.w + x1.w * sn.w) * scl;
        __half2 lo0 = __floats2half2_rn(o0x, o0y);
        __half2 lo1 = __floats2half2_rn(o0z, o0w);
        __half2 hi0 = __floats2half2_rn(o1x, o1y);
        __half2 hi1 = __floats2half2_rn(o1z, o1w);
        uint2 pk0 = make_uint2(h2_as_u32(lo0), h2_as_u32(lo1));
        uint2 pk1 = make_uint2(h2_as_u32(hi0), h2_as_u32(hi1));
        *(uint2*)&outp[(size_t)r * HD_ + c4]      = pk0;
        *(uint2*)&outp[(size_t)r * HD_ + c4 + 64] = pk1;
    }
}

// Plain GEMM (O projection): C fp32 row-major [M,N].
__global__ __launch_bounds__(256, 2)
void gemm_hmma_kernel(const __half* __restrict__ A, const __half* __restrict__ Bw,
                      float* __restrict__ C, int M, int N, int K) {
    extern __shared__ __align__(128) char dsm[];
    uint32_t sBase = smem_u32(dsm);
    int tid = threadIdx.x;
    int m0 = blockIdx.y * 128, n0 = blockIdx.x * 128;

    float acc[4][4][4];
#pragma unroll
    for (int mt = 0; mt < 4; mt++)
#pragma unroll
        for (int nt = 0; nt < 4; nt++)
#pragma unroll
            for (int i = 0; i < 4; i++) acc[mt][nt][i] = 0.f;

    gemm_mainloop(A, Bw, m0, n0, K, sBase, tid, acc);

    int wid = tid >> 5, l = tid & 31;
    int warpM = wid >> 2, warpN = wid & 3;
    int rl0 = warpM * 64 + (l >> 2);
    int cl0 = warpN * 32 + (l & 3) * 2;
    float* Cb = C + (size_t)m0 * N + n0;
#pragma unroll
    for (int mt = 0; mt < 4; mt++)
#pragma unroll
        for (int nt = 0; nt < 4; nt++) {
            float* d0 = Cb + (size_t)(rl0 + mt * 16) * N + cl0 + nt * 8;
            float* d1 = d0 + (size_t)8 * N;
            *(float2*)d0 = make_float2(acc[mt][nt][0], acc[mt][nt][1]);
            *(float2*)d1 = make_float2(acc[mt][nt][2], acc[mt][nt][3]);
        }
}

// ---------------------------------------------------------------------------
// Flash attention, HMMA fp16, causal. Br=128, Bc=64, 256 threads (8 warps).
// (R13/R14/R16-proven, unchanged)
// ---------------------------------------------------------------------------
#define FPITCH 272
#define FTILE (64 * FPITCH)            // K/V tile: 64 rows
#define FQTILE (128 * FPITCH)          // Q tile: 128 rows
#define FLASH_DSMEM (FQTILE + 4 * FTILE)   // 104448

__device__ __forceinline__ void flash_fill_kv(uint32_t sbuf, const __half* src,
                                              int tid) {
#pragma unroll
    for (int i = 0; i < 4; i++) {
        int v = tid + i * 256;          // 0..1023
        int row = v >> 4, c = v & 15;
        cp_async16(sbuf + (uint32_t)row * FPITCH + (uint32_t)c * 16,
                   src + (size_t)row * HD_ + c * 8);
    }
}
__device__ __forceinline__ void flash_fill_q(uint32_t sbuf, const __half* src,
                                             int tid) {
#pragma unroll
    for (int i = 0; i < 8; i++) {
        int v = tid + i * 256;          // 0..2047
        int row = v >> 4, c = v & 15;
        cp_async16(sbuf + (uint32_t)row * FPITCH + (uint32_t)c * 16,
                   src + (size_t)row * HD_ + c * 8);
    }
}

__global__ __launch_bounds__(256, 1)
void flash_hmma_kernel(const __half* __restrict__ Q, const __half* __restrict__ Kg,
                       const __half* __restrict__ Vg, __half* __restrict__ AO) {
    extern __shared__ __align__(128) char dsm[];
    uint32_t sQ = smem_u32(dsm);
    uint32_t sK0 = sQ + FQTILE;
    uint32_t sV0 = sQ + FQTILE + 2 * FTILE;

    int tid = threadIdx.x;
    int w = tid >> 5, l = tid & 31;
    int qt = gridDim.x - 1 - blockIdx.x;   // heavy tiles first
    int bh = blockIdx.y;
    int b = bh / H_, h = bh % H_;
    int kh = h / (H_ / KV_);

    const __half* Qp = Q + ((size_t)(b * H_ + h) * S_ + qt * 128) * HD_;
    const __half* Kp = Kg + ((size_t)(b * KV_ + kh) * S_) * HD_;
    const __half* Vp = Vg + ((size_t)(b * KV_ + kh) * S_) * HD_;

    int ntiles = 2 * qt + 2;

    flash_fill_q(sQ, Qp, tid);
    flash_fill_kv(sK0, Kp, tid);
    flash_fill_kv(sV0, Vp, tid);
    CP_COMMIT();

    uint32_t laneOff = (uint32_t)(l & 15) * FPITCH + (uint32_t)(l >> 4) * 16;

    uint32_t Qf[8][4];
    float O[16][4];
#pragma unroll
    for (int nf = 0; nf < 16; nf++)
#pragma unroll
        for (int i = 0; i < 4; i++) O[nf][i] = 0.f;
    float m0 = -1e30f, m1 = -1e30f, l0 = 0.f, l1 = 0.f;

    int lq = l >> 2;
    int lc2 = (l & 3) * 2;

    for (int j = 0; j < ntiles; j++) {
        int buf = j & 1;
        if (j + 1 < ntiles) {
            int nbuf = (j + 1) & 1;
            flash_fill_kv(sK0 + nbuf * FTILE, Kp + (size_t)(j + 1) * 64 * HD_, tid);
            flash_fill_kv(sV0 + nbuf * FTILE, Vp + (size_t)(j + 1) * 64 * HD_, tid);
            CP_COMMIT();
            cp_wait<1>();
        } else {
            cp_wait<0>();
        }
        __syncthreads();

        if (j == 0) {
            uint32_t qb = sQ + (uint32_t)(w * 16) * FPITCH + laneOff;
#pragma unroll
            for (int kc = 0; kc < 8; kc++) ldsm_x4(Qf[kc], qb + kc * 32);
        }

        // Last diagonal sub-tile is entirely above the diagonal for warps 0-3:
        // skipping is an exact no-op (m,l,O unchanged).
        bool active = !(j == 2 * qt + 1 && w < 4);
        if (active) {
            float sacc[8][4];
#pragma unroll
            for (int nf = 0; nf < 8; nf++)
#pragma unroll
                for (int i = 0; i < 4; i++) sacc[nf][i] = 0.f;

            uint32_t kb = sK0 + (uint32_t)buf * FTILE + laneOff;
#pragma unroll
            for (int kc = 0; kc < 8; kc++) {
#pragma unroll
                for (int g = 0; g < 4; g++) {
                    uint32_t r[4];
                    ldsm_x4(r, kb + (uint32_t)(g * 16) * FPITCH + kc * 32);
                    uint32_t b0[2] = {r[0], r[2]}, b1[2] = {r[1], r[3]};
                    mma16816(sacc[2 * g], Qf[kc], b0);
                    mma16816(sacc[2 * g + 1], Qf[kc], b1);
                }
            }

            if (j >= 2 * qt) {
                int lr0 = qt * 128 + w * 16 + lq, lr1 = lr0 + 8;
                int cb = j * 64;
#pragma unroll
                for (int nf = 0; nf < 8; nf++) {
                    int c0 = cb + nf * 8 + lc2;
                    if (c0 > lr0) sacc[nf][0] = -1e30f;
                    if (c0 + 1 > lr0) sacc[nf][1] = -1e30f;
                    if (c0 > lr1) sacc[nf][2] = -1e30f;
                    if (c0 + 1 > lr1) sacc[nf][3] = -1e30f;
                }
            }

            float mx0 = -1e30f, mx1 = -1e30f;
#pragma unroll
            for (int nf = 0; nf < 8; nf++) {
                mx0 = fmaxf(mx0, fmaxf(sacc[nf][0], sacc[nf][1]));
                mx1 = fmaxf(mx1, fmaxf(sacc[nf][2], sacc[nf][3]));
            }
            mx0 = fmaxf(mx0, __shfl_xor_sync(0xffffffffu, mx0, 1));
            mx0 = fmaxf(mx0, __shfl_xor_sync(0xffffffffu, mx0, 2));
            mx1 = fmaxf(mx1, __shfl_xor_sync(0xffffffffu, mx1, 1));
            mx1 = fmaxf(mx1, __shfl_xor_sync(0xffffffffu, mx1, 2));
            float m0n = fmaxf(m0, mx0), m1n = fmaxf(m1, mx1);
            float f0 = __expf(m0 - m0n), f1 = __expf(m1 - m1n);

            uint32_t Pf[4][4];
            float s0 = 0.f, s1 = 0.f;
#pragma unroll
            for (int kc = 0; kc < 4; kc++) {
                float pa = __expf(sacc[2 * kc][0] - m0n);
                float pb = __expf(sacc[2 * kc][1] - m0n);
                float pc = __expf(sacc[2 * kc][2] - m1n);
                float pd = __expf(sacc[2 * kc][3] - m1n);
                float pe = __expf(sacc[2 * kc + 1][0] - m0n);
                float pf = __expf(sacc[2 * kc + 1][1] - m0n);
                float pg = __expf(sacc[2 * kc + 1][2] - m1n);
                float ph = __expf(sacc[2 * kc + 1][3] - m1n);
                s0 += pa + pb + pe + pf;
                s1 += pc + pd + pg + ph;
                Pf[kc][0] = h2_as_u32(__floats2half2_rn(pa, pb));
                Pf[kc][1] = h2_as_u32(__floats2half2_rn(pc, pd));
                Pf[kc][2] = h2_as_u32(__floats2half2_rn(pe, pf));
                Pf[kc][3] = h2_as_u32(__floats2half2_rn(pg, ph));
            }
            l0 = l0 * f0 + s0;
            l1 = l1 * f1 + s1;
            m0 = m0n; m1 = m1n;

#pragma unroll
            for (int nf = 0; nf < 16; nf++) {
                O[nf][0] *= f0; O[nf][1] *= f0;
                O[nf][2] *= f1; O[nf][3] *= f1;
            }

            uint32_t vb = sV0 + (uint32_t)buf * FTILE + laneOff;
#pragma unroll
            for (int kc = 0; kc < 4; kc++) {
#pragma unroll
                for (int g = 0; g < 8; g++) {
                    uint32_t r[4];
                    ldsm_x4_t(r, vb + (uint32_t)(kc * 16) * FPITCH + g * 32);
                    uint32_t b0[2] = {r[0], r[1]}, b1[2] = {r[2], r[3]};
                    mma16816(O[2 * g], Pf[kc], b0);
                    mma16816(O[2 * g + 1], Pf[kc], b1);
                }
            }
        }
        __syncthreads();
    }

    l0 += __shfl_xor_sync(0xffffffffu, l0, 1);
    l0 += __shfl_xor_sync(0xffffffffu, l0, 2);
    l1 += __shfl_xor_sync(0xffffffffu, l1, 1);
    l1 += __shfl_xor_sync(0xffffffffu, l1, 2);
    float inv0 = 1.0f / l0, inv1 = 1.0f / l1;

    int row0 = qt * 128 + w * 16 + lq;
    __half* base0 = AO + ((size_t)(b * S_ + row0) * H_ + h) * HD_;
    __half* base1 = AO + ((size_t)(b * S_ + row0 + 8) * H_ + h) * HD_;
#pragma unroll
    for (int nf = 0; nf < 16; nf++) {
        int c0 = nf * 8 + lc2;
        *(__half2*)(base0 + c0) = __floats2half2_rn(O[nf][0] * inv0, O[nf][1] * inv0);
        *(__half2*)(base1 + c0) = __floats2half2_rn(O[nf][2] * inv1, O[nf][3] * inv1);
    }
}

// ---------------------------------------------------------------------------
extern "C" void kernel_launch(void* const* d_in, const int* in_sizes, int n_in,
                              void* d_out, int out_size) {
    const float* hs  = (const float*)d_in[0];
    const float* Wq  = (const float*)d_in[1];
    const float* Wk  = (const float*)d_in[2];
    const float* Wv  = (const float*)d_in[3];
    const float* Wo  = (const float*)d_in[4];
    const int*   pos = (const int*)d_in[5];
    float* out = (float*)d_out;

    __half *hsH, *WqH, *WkH, *WvH, *WoH, *QH, *KH, *VH, *AOH;
    cudaGetSymbolAddress((void**)&hsH, g_hsH);
    cudaGetSymbolAddress((void**)&WqH, g_WqH);
    cudaGetSymbolAddress((void**)&WkH, g_WkH);
    cudaGetSymbolAddress((void**)&WvH, g_WvH);
    cudaGetSymbolAddress((void**)&WoH, g_WoH);
    cudaGetSymbolAddress((void**)&QH, g_QH);
    cudaGetSymbolAddress((void**)&KH, g_KH);
    cudaGetSymbolAddress((void**)&VH, g_VH);
    cudaGetSymbolAddress((void**)&AOH, g_AOH);

    cudaFuncSetAttribute(qkv_hmma_kernel,
                         cudaFuncAttributeMaxDynamicSharedMemorySize, GEMM_DSMEM);
    cudaFuncSetAttribute(gemm_hmma_kernel,
                         cudaFuncAttributeMaxDynamicSharedMemorySize, GEMM_DSMEM);
    cudaFuncSetAttribute(flash_hmma_kernel,
                         cudaFuncAttributeMaxDynamicSharedMemorySize, FLASH_DSMEM);

    // RoPE tables (needed by qkv epilogue)
    rope_table_kernel<<<(B_ * S_ * 64 + 255) / 256, 256>>>(pos);

    // All fp32 -> fp16 conversions in one launch (MLP=4 per segment)
    convert_all_kernel<<<(CVT_THREADS + 255) / 256, 256>>>(
        hs, Wq, Wk, Wv, Wo, hsH, WqH, WkH, WvH, WoH);

    // Fused QKV projections + RoPE (48 x 32 = 1536 CTAs, 128-row m-tiles)
    qkv_hmma_kernel<<<dim3(48, (B_ * S_) / 128), 256, GEMM_DSMEM>>>(
        hsH, WqH, WkH, WvH, QH, KH, VH);

    // Flash attention (HMMA, causal, Br=128)
    flash_hmma_kernel<<<dim3(S_ / 128, B_ * H_), 256, FLASH_DSMEM>>>(
        QH, KH, VH, AOH);

    // Output projection (32 x 32 = 1024 CTAs, 128-row m-tiles)
    gemm_hmma_kernel<<<dim3(D_ / 128, (B_ * S_) / 128), 256, GEMM_DSMEM>>>(
        AOH, WoH, out, B_ * S_, D_, H_ * HD_);
}